// round 2
// baseline (speedup 1.0000x reference)
#include <cuda_runtime.h>
#include <math.h>

// Batched log(A) for SPD 64x64 via Chebyshev/Clenshaw matrix polynomial.
// Round 2: packed fma.rn.f32x2 (FFMA2) + 4x8 register tiles (128 thr/matrix),
// B-operand loaded straight from smem as packed f32x2 pairs (ld.shared.v2.u64).

#define DEG 36
#define NN  64

__device__ __forceinline__ unsigned long long ffma2(unsigned long long a,
                                                    unsigned long long b,
                                                    unsigned long long c) {
    unsigned long long d;
    asm("fma.rn.f32x2 %0, %1, %2, %3;" : "=l"(d) : "l"(a), "l"(b), "l"(c));
    return d;
}
__device__ __forceinline__ unsigned long long dup2(float a) {
    unsigned long long d;
    asm("mov.b64 %0, {%1, %1};" : "=l"(d) : "f"(a));
    return d;
}
__device__ __forceinline__ void unpack2(unsigned long long v, float& lo, float& hi) {
    asm("mov.b64 {%0, %1}, %2;" : "=f"(lo), "=f"(hi) : "l"(v));
}

__global__ __launch_bounds__(128, 4)
void logm_cheb_kernel(const float* __restrict__ A, float* __restrict__ Out)
{
    __shared__ __align__(16) float Ah[NN * NN];        // Ahat (symmetric)
    __shared__ __align__(16) float Bb[2][NN * NN];     // Clenshaw b1 / b2

    const int tid = threadIdx.x;
    const int mat = blockIdx.x;

    const float lo  = 0.09f, hi = 5.30f;
    const float h   = 0.5f * (hi - lo);
    const float mid = 0.5f * (hi + lo);
    const float u   = mid / h;
    const float rho = u + sqrtf(u * u - 1.0f);
    const float alpha = 1.0f / h;          // t = alpha*x - u

    const float cK   = ((DEG & 1) ? 2.0f : -2.0f) * powf(rho, -(float)DEG) / (float)DEG;
    const float cKm1 = (((DEG - 1) & 1) ? 2.0f : -2.0f) * powf(rho, -(float)(DEG - 1)) / (float)(DEG - 1);
    const float c0   = logf(h * rho * 0.5f);

    // ---- Load A, build Ahat = alpha*A - u*I, init Clenshaw state ----
    {
        const float4* Ag = (const float4*)(A + (size_t)mat * (NN * NN));
        float4* Ah4 = (float4*)Ah;
        float4* B04 = (float4*)Bb[0];
        float4* B14 = (float4*)Bb[1];
        #pragma unroll
        for (int r = 0; r < 8; ++r) {
            int q = tid + r * 128;          // float4 index, 0..1023
            float4 v = Ag[q];
            int e = q << 2;
            int i = e >> 6;
            int j = e & 63;
            float dx = (j + 0 == i) ? 1.0f : 0.0f;
            float dy = (j + 1 == i) ? 1.0f : 0.0f;
            float dz = (j + 2 == i) ? 1.0f : 0.0f;
            float dw = (j + 3 == i) ? 1.0f : 0.0f;
            v.x = alpha * v.x - u * dx;
            v.y = alpha * v.y - u * dy;
            v.z = alpha * v.z - u * dz;
            v.w = alpha * v.w - u * dw;
            Ah4[q] = v;
            float4 b0, b1;
            b0.x = 2.0f * cK * v.x + cKm1 * dx;
            b0.y = 2.0f * cK * v.y + cKm1 * dy;
            b0.z = 2.0f * cK * v.z + cKm1 * dz;
            b0.w = 2.0f * cK * v.w + cKm1 * dw;
            b1.x = cK * dx;  b1.y = cK * dy;  b1.z = cK * dz;  b1.w = cK * dw;
            B04[q] = b0;
            B14[q] = b1;
        }
    }
    __syncthreads();

    // Thread tile: 4 rows x 8 cols.  16 row-groups x 8 col-groups = 128 threads.
    const int i0 = (tid >> 3) << 2;        // 0..60 step 4
    const int j0 = (tid & 7) << 3;         // 0..56 step 8

    // shared-state base addresses (32-bit shared window)
    const unsigned sB0 = (unsigned)__cvta_generic_to_shared(Bb[0]);
    const unsigned sB1 = (unsigned)__cvta_generic_to_shared(Bb[1]);

    int cur = 0;                            // index of b_{k+1}
    float rp = powf(rho, -(float)(DEG - 2));

    for (int k = DEG - 2; k >= 0; --k) {
        const int oth = cur ^ 1;
        const unsigned sBc = (cur ? sB1 : sB0) + (unsigned)(j0 << 2);

        unsigned long long acc[4][4];
        #pragma unroll
        for (int r = 0; r < 4; ++r)
            #pragma unroll
            for (int p = 0; p < 4; ++p) acc[r][p] = 0ULL;

        // C = Ahat * b1.  Ahat symmetric: column i0.. of Ahat == row-contig reads.
        #pragma unroll 16
        for (int kk = 0; kk < NN; ++kk) {
            float4 av = *(const float4*)(Ah + kk * NN + i0);
            unsigned long long b01, b23, b45, b67;
            unsigned addr = sBc + (unsigned)(kk * NN * 4);
            asm("ld.shared.v2.u64 {%0,%1}, [%2];"      : "=l"(b01), "=l"(b23) : "r"(addr));
            asm("ld.shared.v2.u64 {%0,%1}, [%2+16];"   : "=l"(b45), "=l"(b67) : "r"(addr));
            unsigned long long a0 = dup2(av.x);
            unsigned long long a1 = dup2(av.y);
            unsigned long long a2 = dup2(av.z);
            unsigned long long a3 = dup2(av.w);
            acc[0][0] = ffma2(a0, b01, acc[0][0]);
            acc[0][1] = ffma2(a0, b23, acc[0][1]);
            acc[0][2] = ffma2(a0, b45, acc[0][2]);
            acc[0][3] = ffma2(a0, b67, acc[0][3]);
            acc[1][0] = ffma2(a1, b01, acc[1][0]);
            acc[1][1] = ffma2(a1, b23, acc[1][1]);
            acc[1][2] = ffma2(a1, b45, acc[1][2]);
            acc[1][3] = ffma2(a1, b67, acc[1][3]);
            acc[2][0] = ffma2(a2, b01, acc[2][0]);
            acc[2][1] = ffma2(a2, b23, acc[2][1]);
            acc[2][2] = ffma2(a2, b45, acc[2][2]);
            acc[2][3] = ffma2(a2, b67, acc[2][3]);
            acc[3][0] = ffma2(a3, b01, acc[3][0]);
            acc[3][1] = ffma2(a3, b23, acc[3][1]);
            acc[3][2] = ffma2(a3, b45, acc[3][2]);
            acc[3][3] = ffma2(a3, b67, acc[3][3]);
        }

        if (k >= 1) {
            const float ck = ((k & 1) ? 2.0f : -2.0f) * rp / (float)k;
            float* __restrict__ Bo = Bb[oth];
            #pragma unroll
            for (int r = 0; r < 4; ++r) {
                const int row = i0 + r;
                float c[8];
                unpack2(acc[r][0], c[0], c[1]);
                unpack2(acc[r][1], c[2], c[3]);
                unpack2(acc[r][2], c[4], c[5]);
                unpack2(acc[r][3], c[6], c[7]);
                float4 p0 = *(const float4*)(Bo + row * NN + j0);
                float4 p1 = *(const float4*)(Bo + row * NN + j0 + 4);
                float4 o0, o1;
                o0.x = 2.0f * c[0] - p0.x + ((row == j0 + 0) ? ck : 0.0f);
                o0.y = 2.0f * c[1] - p0.y + ((row == j0 + 1) ? ck : 0.0f);
                o0.z = 2.0f * c[2] - p0.z + ((row == j0 + 2) ? ck : 0.0f);
                o0.w = 2.0f * c[3] - p0.w + ((row == j0 + 3) ? ck : 0.0f);
                o1.x = 2.0f * c[4] - p1.x + ((row == j0 + 4) ? ck : 0.0f);
                o1.y = 2.0f * c[5] - p1.y + ((row == j0 + 5) ? ck : 0.0f);
                o1.z = 2.0f * c[6] - p1.z + ((row == j0 + 6) ? ck : 0.0f);
                o1.w = 2.0f * c[7] - p1.w + ((row == j0 + 7) ? ck : 0.0f);
                *(float4*)(Bo + row * NN + j0)     = o0;
                *(float4*)(Bo + row * NN + j0 + 4) = o1;
            }
            rp *= rho;
            cur = oth;
            __syncthreads();
        } else {
            // final: out = Ahat*b1 - b2 + c0*I
            float* __restrict__ Og = Out + (size_t)mat * (NN * NN);
            const float* __restrict__ Bo = Bb[oth];
            #pragma unroll
            for (int r = 0; r < 4; ++r) {
                const int row = i0 + r;
                float c[8];
                unpack2(acc[r][0], c[0], c[1]);
                unpack2(acc[r][1], c[2], c[3]);
                unpack2(acc[r][2], c[4], c[5]);
                unpack2(acc[r][3], c[6], c[7]);
                float4 p0 = *(const float4*)(Bo + row * NN + j0);
                float4 p1 = *(const float4*)(Bo + row * NN + j0 + 4);
                float4 o0, o1;
                o0.x = c[0] - p0.x + ((row == j0 + 0) ? c0 : 0.0f);
                o0.y = c[1] - p0.y + ((row == j0 + 1) ? c0 : 0.0f);
                o0.z = c[2] - p0.z + ((row == j0 + 2) ? c0 : 0.0f);
                o0.w = c[3] - p0.w + ((row == j0 + 3) ? c0 : 0.0f);
                o1.x = c[4] - p1.x + ((row == j0 + 4) ? c0 : 0.0f);
                o1.y = c[5] - p1.y + ((row == j0 + 5) ? c0 : 0.0f);
                o1.z = c[6] - p1.z + ((row == j0 + 6) ? c0 : 0.0f);
                o1.w = c[7] - p1.w + ((row == j0 + 7) ? c0 : 0.0f);
                *(float4*)(Og + row * NN + j0)     = o0;
                *(float4*)(Og + row * NN + j0 + 4) = o1;
            }
        }
    }
}

extern "C" void kernel_launch(void* const* d_in, const int* in_sizes, int n_in,
                              void* d_out, int out_size) {
    const float* x = (const float*)d_in[0];
    float* out = (float*)d_out;
    int nmat = in_sizes[0] / (NN * NN);
    logm_cheb_kernel<<<nmat, 128>>>(x, out);
}

// round 3
// speedup vs baseline: 1.4589x; 1.4589x over previous
#include <cuda_runtime.h>
#include <math.h>

// Batched log(A) for SPD 64x64 via Chebyshev/Clenshaw (DEG=26, 25 matmuls).
// Warp = 32 rows x 32 cols: B loads are warp-broadcast (conflict-free),
// A loads via symmetry are coalesced LDS.32. b2 lives in registers; b1 is
// updated in place (read-own-tile + 2 syncs), so smem = A + one B buffer
// -> 5 blocks/SM. FFMA2 (fma.rn.f32x2) for the inner product.

#define DEG 26
#define NN  64
#define LDP 68   // padded row stride (floats): 16B-aligned, bank-staggered

__device__ __forceinline__ unsigned long long ffma2(unsigned long long a,
                                                    unsigned long long b,
                                                    unsigned long long c) {
    unsigned long long d;
    asm("fma.rn.f32x2 %0, %1, %2, %3;" : "=l"(d) : "l"(a), "l"(b), "l"(c));
    return d;
}
__device__ __forceinline__ unsigned long long dup2(float a) {
    unsigned long long d;
    asm("mov.b64 %0, {%1, %1};" : "=l"(d) : "f"(a));
    return d;
}
__device__ __forceinline__ void unpack2(unsigned long long v, float& lo, float& hi) {
    asm("mov.b64 {%0, %1}, %2;" : "=f"(lo), "=f"(hi) : "l"(v));
}
__device__ __forceinline__ unsigned long long pack2(float lo, float hi) {
    unsigned long long d;
    asm("mov.b64 %0, {%1, %2};" : "=l"(d) : "f"(lo), "f"(hi));
    return d;
}

__global__ __launch_bounds__(128, 5)
void logm_cheb_kernel(const float* __restrict__ A, float* __restrict__ Out)
{
    __shared__ __align__(16) float Ah[NN * LDP];   // Ahat, padded stride
    __shared__ __align__(16) float Bs[NN * LDP];   // Clenshaw b1 (in-place)

    const int tid  = threadIdx.x;
    const int mat  = blockIdx.x;
    const int warp = tid >> 5;
    const int lane = tid & 31;
    const int row  = ((warp >> 1) << 5) | lane;    // 0..63
    const int c0   = (warp & 1) << 5;              // 0 or 32

    const float lo  = 0.09f, hi = 5.30f;
    const float h   = 0.5f * (hi - lo);
    const float mid = 0.5f * (hi + lo);
    const float u   = mid / h;
    const float rho = u + sqrtf(u * u - 1.0f);
    const float alpha = 1.0f / h;                  // t = alpha*x - u

    const float cK   = ((DEG & 1) ? 2.0f : -2.0f) * powf(rho, -(float)DEG) / (float)DEG;
    const float cKm1 = (((DEG - 1) & 1) ? 2.0f : -2.0f) * powf(rho, -(float)(DEG - 1)) / (float)(DEG - 1);
    const float c0f  = logf(h * rho * 0.5f);

    // ---- Load A, build Ahat = alpha*A - u*I, init b1 = cKm1*I + 2*cK*Ahat ----
    {
        const float4* Ag = (const float4*)(A + (size_t)mat * (NN * NN));
        #pragma unroll
        for (int r = 0; r < 8; ++r) {
            int q = tid + (r << 7);               // float4 index 0..1023
            float4 v = Ag[q];
            int i = q >> 4;
            int j = (q & 15) << 2;
            float dx = (j + 0 == i) ? 1.0f : 0.0f;
            float dy = (j + 1 == i) ? 1.0f : 0.0f;
            float dz = (j + 2 == i) ? 1.0f : 0.0f;
            float dw = (j + 3 == i) ? 1.0f : 0.0f;
            v.x = alpha * v.x - u * dx;
            v.y = alpha * v.y - u * dy;
            v.z = alpha * v.z - u * dz;
            v.w = alpha * v.w - u * dw;
            *(float4*)(Ah + i * LDP + j) = v;
            float4 b;
            b.x = 2.0f * cK * v.x + cKm1 * dx;
            b.y = 2.0f * cK * v.y + cKm1 * dy;
            b.z = 2.0f * cK * v.z + cKm1 * dz;
            b.w = 2.0f * cK * v.w + cKm1 * dw;
            *(float4*)(Bs + i * LDP + j) = b;
        }
    }
    // b2 = cK * I (thread's own tile, packed pairs)
    unsigned long long b2[16];
    #pragma unroll
    for (int p = 0; p < 16; ++p) {
        int cl = c0 + 2 * p;
        b2[p] = pack2((row == cl) ? cK : 0.0f, (row == cl + 1) ? cK : 0.0f);
    }
    __syncthreads();

    const unsigned sA = (unsigned)__cvta_generic_to_shared(Ah) + (unsigned)(row << 2);
    const unsigned sB = (unsigned)__cvta_generic_to_shared(Bs) + (unsigned)(c0 << 2);

    float rp = powf(rho, -(float)(DEG - 2));

    for (int k = DEG - 2; k >= 0; --k) {
        unsigned long long acc[16];
        #pragma unroll
        for (int p = 0; p < 16; ++p) acc[p] = 0ULL;

        unsigned aA = sA, bA = sB;
        #pragma unroll 8
        for (int kk = 0; kk < NN; ++kk) {
            float a;
            asm("ld.shared.f32 %0, [%1];" : "=f"(a) : "r"(aA));
            unsigned long long a2 = dup2(a);
            unsigned long long v0, v1;
            asm("ld.shared.v2.u64 {%0,%1}, [%2];"     : "=l"(v0), "=l"(v1) : "r"(bA));
            acc[0]  = ffma2(a2, v0, acc[0]);
            acc[1]  = ffma2(a2, v1, acc[1]);
            asm("ld.shared.v2.u64 {%0,%1}, [%2+16];"  : "=l"(v0), "=l"(v1) : "r"(bA));
            acc[2]  = ffma2(a2, v0, acc[2]);
            acc[3]  = ffma2(a2, v1, acc[3]);
            asm("ld.shared.v2.u64 {%0,%1}, [%2+32];"  : "=l"(v0), "=l"(v1) : "r"(bA));
            acc[4]  = ffma2(a2, v0, acc[4]);
            acc[5]  = ffma2(a2, v1, acc[5]);
            asm("ld.shared.v2.u64 {%0,%1}, [%2+48];"  : "=l"(v0), "=l"(v1) : "r"(bA));
            acc[6]  = ffma2(a2, v0, acc[6]);
            acc[7]  = ffma2(a2, v1, acc[7]);
            asm("ld.shared.v2.u64 {%0,%1}, [%2+64];"  : "=l"(v0), "=l"(v1) : "r"(bA));
            acc[8]  = ffma2(a2, v0, acc[8]);
            acc[9]  = ffma2(a2, v1, acc[9]);
            asm("ld.shared.v2.u64 {%0,%1}, [%2+80];"  : "=l"(v0), "=l"(v1) : "r"(bA));
            acc[10] = ffma2(a2, v0, acc[10]);
            acc[11] = ffma2(a2, v1, acc[11]);
            asm("ld.shared.v2.u64 {%0,%1}, [%2+96];"  : "=l"(v0), "=l"(v1) : "r"(bA));
            acc[12] = ffma2(a2, v0, acc[12]);
            acc[13] = ffma2(a2, v1, acc[13]);
            asm("ld.shared.v2.u64 {%0,%1}, [%2+112];" : "=l"(v0), "=l"(v1) : "r"(bA));
            acc[14] = ffma2(a2, v0, acc[14]);
            acc[15] = ffma2(a2, v1, acc[15]);
            aA += LDP * 4;
            bA += LDP * 4;
        }

        if (k >= 1) {
            // read own tile of current b1 (becomes next b2)
            unsigned long long old[16];
            {
                const float* Bp = Bs + row * LDP + c0;
                #pragma unroll
                for (int q = 0; q < 8; ++q) {
                    float4 t = *(const float4*)(Bp + 4 * q);
                    old[2 * q]     = pack2(t.x, t.y);
                    old[2 * q + 1] = pack2(t.z, t.w);
                }
            }
            __syncthreads();   // everyone done reading b1

            const float ck = ((k & 1) ? 2.0f : -2.0f) * rp / (float)k;
            float* Bp = Bs + row * LDP + c0;
            #pragma unroll
            for (int q = 0; q < 8; ++q) {
                float a0, a1, a2f, a3, o0, o1, o2, o3;
                unpack2(acc[2 * q],     a0, a1);
                unpack2(acc[2 * q + 1], a2f, a3);
                unpack2(b2[2 * q],      o0, o1);
                unpack2(b2[2 * q + 1],  o2, o3);
                int cl = c0 + 4 * q;
                float4 nv;
                nv.x = 2.0f * a0  - o0 + ((row == cl + 0) ? ck : 0.0f);
                nv.y = 2.0f * a1  - o1 + ((row == cl + 1) ? ck : 0.0f);
                nv.z = 2.0f * a2f - o2 + ((row == cl + 2) ? ck : 0.0f);
                nv.w = 2.0f * a3  - o3 + ((row == cl + 3) ? ck : 0.0f);
                *(float4*)(Bp + 4 * q) = nv;
                b2[2 * q]     = old[2 * q];
                b2[2 * q + 1] = old[2 * q + 1];
            }
            rp *= rho;
            __syncthreads();   // new b1 visible
        } else {
            // final: out = Ahat*b1 - b2 + c0f*I
            float* Og = Out + (size_t)mat * (NN * NN) + row * NN + c0;
            #pragma unroll
            for (int q = 0; q < 8; ++q) {
                float a0, a1, a2f, a3, o0, o1, o2, o3;
                unpack2(acc[2 * q],     a0, a1);
                unpack2(acc[2 * q + 1], a2f, a3);
                unpack2(b2[2 * q],      o0, o1);
                unpack2(b2[2 * q + 1],  o2, o3);
                int cl = c0 + 4 * q;
                float4 nv;
                nv.x = a0  - o0 + ((row == cl + 0) ? c0f : 0.0f);
                nv.y = a1  - o1 + ((row == cl + 1) ? c0f : 0.0f);
                nv.z = a2f - o2 + ((row == cl + 2) ? c0f : 0.0f);
                nv.w = a3  - o3 + ((row == cl + 3) ? c0f : 0.0f);
                *(float4*)(Og + 4 * q) = nv;
            }
        }
    }
}

extern "C" void kernel_launch(void* const* d_in, const int* in_sizes, int n_in,
                              void* d_out, int out_size) {
    const float* x = (const float*)d_in[0];
    float* out = (float*)d_out;
    int nmat = in_sizes[0] / (NN * NN);
    logm_cheb_kernel<<<nmat, 128>>>(x, out);
}

// round 5
// speedup vs baseline: 2.7999x; 1.9192x over previous
#include <cuda_runtime.h>
#include <math.h>

// Batched log(A) for SPD 64x64 via Chebyshev/Clenshaw (DEG=24, 23 matmuls).
// 64 threads/matrix, 8x8 split register tiles (rows {4ti,32+4ti}+0..3,
// cols {4tj,32+4tj}+0..3) so every LDS.128 phase is either uniform (A, via
// symmetry) or a contiguous conflict-free 128B (B). 4 LDS per 64 FMA.
// b2 kept in registers; b1 updated in place in smem (2 barriers/iter).

#define DEG 24
#define NN  64
typedef unsigned long long ull;

__device__ __forceinline__ ull ffma2(ull a, ull b, ull c) {
    ull d;
    asm("fma.rn.f32x2 %0, %1, %2, %3;" : "=l"(d) : "l"(a), "l"(b), "l"(c));
    return d;
}
__device__ __forceinline__ ull dup2(float a) {
    ull d;
    asm("mov.b64 %0, {%1, %1};" : "=l"(d) : "f"(a));
    return d;
}
__device__ __forceinline__ void unpack2(ull v, float& lo, float& hi) {
    asm("mov.b64 {%0, %1}, %2;" : "=f"(lo), "=f"(hi) : "l"(v));
}
__device__ __forceinline__ ull pack2(float lo, float hi) {
    ull d;
    asm("mov.b64 %0, {%1, %2};" : "=l"(d) : "f"(lo), "f"(hi));
    return d;
}

__global__ __launch_bounds__(64, 6)
void logm_cheb_kernel(const float* __restrict__ A, float* __restrict__ Out)
{
    __shared__ __align__(16) float Ah[NN * NN];   // Ahat (symmetric)
    __shared__ __align__(16) float Bs[NN * NN];   // Clenshaw b1 (in-place)

    const int tid = threadIdx.x;
    const int mat = blockIdx.x;
    const int ti  = tid >> 3;      // 0..7
    const int tj  = tid & 7;       // 0..7

    const float lo  = 0.09f, hi = 5.30f;
    const float h   = 0.5f * (hi - lo);
    const float mid = 0.5f * (hi + lo);
    const float u   = mid / h;
    const float rho = u + sqrtf(u * u - 1.0f);
    const float alpha = 1.0f / h;

    const float cK   = ((DEG & 1) ? 2.0f : -2.0f) * powf(rho, -(float)DEG) / (float)DEG;
    const float cKm1 = (((DEG - 1) & 1) ? 2.0f : -2.0f) * powf(rho, -(float)(DEG - 1)) / (float)(DEG - 1);
    const float c0f  = logf(h * rho * 0.5f);

    // ---- Load A, build Ahat = alpha*A - u*I, init b1 = cKm1*I + 2*cK*Ahat ----
    {
        const float4* Ag = (const float4*)(A + (size_t)mat * (NN * NN));
        #pragma unroll
        for (int r = 0; r < 16; ++r) {
            int q = tid + (r << 6);              // float4 index 0..1023
            float4 v = Ag[q];
            int i = q >> 4;
            int j = (q & 15) << 2;
            float dx = (j + 0 == i) ? 1.0f : 0.0f;
            float dy = (j + 1 == i) ? 1.0f : 0.0f;
            float dz = (j + 2 == i) ? 1.0f : 0.0f;
            float dw = (j + 3 == i) ? 1.0f : 0.0f;
            v.x = alpha * v.x - u * dx;
            v.y = alpha * v.y - u * dy;
            v.z = alpha * v.z - u * dz;
            v.w = alpha * v.w - u * dw;
            *(float4*)(Ah + i * NN + j) = v;
            float4 b;
            b.x = 2.0f * cK * v.x + cKm1 * dx;
            b.y = 2.0f * cK * v.y + cKm1 * dy;
            b.z = 2.0f * cK * v.z + cKm1 * dz;
            b.w = 2.0f * cK * v.w + cKm1 * dw;
            *(float4*)(Bs + i * NN + j) = b;
        }
    }

    // Tile coordinates: row(ar) = (ar>=4)*32 + 4*ti + (ar&3), ar=0..7
    //                   colpair(bp): base c = (bp>=2)*32 + 4*tj + 2*(bp&1)
    // b2 = cK * I in tile layout
    ull b2t[8][4];
    #pragma unroll
    for (int ar = 0; ar < 8; ++ar) {
        int row = ((ar & 4) << 3) + (ti << 2) + (ar & 3);
        #pragma unroll
        for (int bp = 0; bp < 4; ++bp) {
            int c = ((bp & 2) << 4) + (tj << 2) + ((bp & 1) << 1);
            b2t[ar][bp] = pack2((row == c) ? cK : 0.0f, (row == c + 1) ? cK : 0.0f);
        }
    }
    __syncthreads();

    const unsigned sA = (unsigned)__cvta_generic_to_shared(Ah) + (unsigned)(ti << 4);
    const unsigned sB = (unsigned)__cvta_generic_to_shared(Bs) + (unsigned)(tj << 4);

    float rp = powf(rho, -(float)(DEG - 2));

    for (int k = DEG - 2; k >= 0; --k) {
        ull acc[8][4];
        #pragma unroll
        for (int ar = 0; ar < 8; ++ar)
            #pragma unroll
            for (int bp = 0; bp < 4; ++bp) acc[ar][bp] = 0ULL;

        unsigned aA = sA, bA = sB;
        #pragma unroll 4
        for (int kk = 0; kk < NN; ++kk) {
            float4 a0, a1;
            asm("ld.shared.v4.f32 {%0,%1,%2,%3}, [%4];"
                : "=f"(a0.x), "=f"(a0.y), "=f"(a0.z), "=f"(a0.w) : "r"(aA));
            asm("ld.shared.v4.f32 {%0,%1,%2,%3}, [%4+128];"
                : "=f"(a1.x), "=f"(a1.y), "=f"(a1.z), "=f"(a1.w) : "r"(aA));
            ull b0, b1v, b2v, b3v;
            asm("ld.shared.v2.u64 {%0,%1}, [%2];"     : "=l"(b0),  "=l"(b1v) : "r"(bA));
            asm("ld.shared.v2.u64 {%0,%1}, [%2+128];" : "=l"(b2v), "=l"(b3v) : "r"(bA));
            ull ad[8];
            ad[0] = dup2(a0.x); ad[1] = dup2(a0.y); ad[2] = dup2(a0.z); ad[3] = dup2(a0.w);
            ad[4] = dup2(a1.x); ad[5] = dup2(a1.y); ad[6] = dup2(a1.z); ad[7] = dup2(a1.w);
            #pragma unroll
            for (int ar = 0; ar < 8; ++ar) {
                acc[ar][0] = ffma2(ad[ar], b0,  acc[ar][0]);
                acc[ar][1] = ffma2(ad[ar], b1v, acc[ar][1]);
                acc[ar][2] = ffma2(ad[ar], b2v, acc[ar][2]);
                acc[ar][3] = ffma2(ad[ar], b3v, acc[ar][3]);
            }
            aA += NN * 4;
            bA += NN * 4;
        }

        __syncthreads();   // all matmul reads of Bs complete

        if (k >= 1) {
            const float ck = ((k & 1) ? 2.0f : -2.0f) * rp / (float)k;
            #pragma unroll
            for (int ar = 0; ar < 8; ++ar) {
                const int row = ((ar & 4) << 3) + (ti << 2) + (ar & 3);
                float* Bp = Bs + row * NN + (tj << 2);
                // read own b1 tile (becomes next b2)
                float4 t0 = *(const float4*)(Bp);
                float4 t1 = *(const float4*)(Bp + 32);
                // compute b_new = 2*acc - b2 + ck*I
                float a0, a1, a2, a3, a4, a5, a6, a7;
                unpack2(acc[ar][0], a0, a1);
                unpack2(acc[ar][1], a2, a3);
                unpack2(acc[ar][2], a4, a5);
                unpack2(acc[ar][3], a6, a7);
                float o0, o1, o2, o3, o4, o5, o6, o7;
                unpack2(b2t[ar][0], o0, o1);
                unpack2(b2t[ar][1], o2, o3);
                unpack2(b2t[ar][2], o4, o5);
                unpack2(b2t[ar][3], o6, o7);
                const int cA = (tj << 2);
                const int cB = 32 + (tj << 2);
                float4 n0, n1;
                n0.x = 2.0f * a0 - o0 + ((row == cA + 0) ? ck : 0.0f);
                n0.y = 2.0f * a1 - o1 + ((row == cA + 1) ? ck : 0.0f);
                n0.z = 2.0f * a2 - o2 + ((row == cA + 2) ? ck : 0.0f);
                n0.w = 2.0f * a3 - o3 + ((row == cA + 3) ? ck : 0.0f);
                n1.x = 2.0f * a4 - o4 + ((row == cB + 0) ? ck : 0.0f);
                n1.y = 2.0f * a5 - o5 + ((row == cB + 1) ? ck : 0.0f);
                n1.z = 2.0f * a6 - o6 + ((row == cB + 2) ? ck : 0.0f);
                n1.w = 2.0f * a7 - o7 + ((row == cB + 3) ? ck : 0.0f);
                *(float4*)(Bp)      = n0;
                *(float4*)(Bp + 32) = n1;
                b2t[ar][0] = pack2(t0.x, t0.y);
                b2t[ar][1] = pack2(t0.z, t0.w);
                b2t[ar][2] = pack2(t1.x, t1.y);
                b2t[ar][3] = pack2(t1.z, t1.w);
            }
            rp *= rho;
            __syncthreads();   // new b1 visible before next matmul
        } else {
            // final: out = Ahat*b1 - b2 + c0f*I
            float* Og = Out + (size_t)mat * (NN * NN);
            #pragma unroll
            for (int ar = 0; ar < 8; ++ar) {
                const int row = ((ar & 4) << 3) + (ti << 2) + (ar & 3);
                float a0, a1, a2, a3, a4, a5, a6, a7;
                unpack2(acc[ar][0], a0, a1);
                unpack2(acc[ar][1], a2, a3);
                unpack2(acc[ar][2], a4, a5);
                unpack2(acc[ar][3], a6, a7);
                float o0, o1, o2, o3, o4, o5, o6, o7;
                unpack2(b2t[ar][0], o0, o1);
                unpack2(b2t[ar][1], o2, o3);
                unpack2(b2t[ar][2], o4, o5);
                unpack2(b2t[ar][3], o6, o7);
                const int cA = (tj << 2);
                const int cB = 32 + (tj << 2);
                float4 n0, n1;
                n0.x = a0 - o0 + ((row == cA + 0) ? c0f : 0.0f);
                n0.y = a1 - o1 + ((row == cA + 1) ? c0f : 0.0f);
                n0.z = a2 - o2 + ((row == cA + 2) ? c0f : 0.0f);
                n0.w = a3 - o3 + ((row == cA + 3) ? c0f : 0.0f);
                n1.x = a4 - o4 + ((row == cB + 0) ? c0f : 0.0f);
                n1.y = a5 - o5 + ((row == cB + 1) ? c0f : 0.0f);
                n1.z = a6 - o6 + ((row == cB + 2) ? c0f : 0.0f);
                n1.w = a7 - o7 + ((row == cB + 3) ? c0f : 0.0f);
                *(float4*)(Og + row * NN + cA) = n0;
                *(float4*)(Og + row * NN + cB) = n1;
            }
        }
    }
}

extern "C" void kernel_launch(void* const* d_in, const int* in_sizes, int n_in,
                              void* d_out, int out_size) {
    const float* x = (const float*)d_in[0];
    float* out = (float*)d_out;
    int nmat = in_sizes[0] / (NN * NN);
    logm_cheb_kernel<<<nmat, 64>>>(x, out);
}

// round 7
// speedup vs baseline: 6.2525x; 2.2331x over previous
#include <cuda_runtime.h>
#include <math.h>

// Batched log(A) for SPD 64x64, degree-23 Chebyshev evaluated with
// Paterson-Stockmeyer in the Chebyshev basis (s=3, k=8):
//   y = T3(Ahat);  p = sum_{i<8} U_i(Ahat) * T_i(y),  U_i = u0 I + u1 A + u2 T2
// -> 9 matmuls (T2, T3, and 7 Clenshaw-in-y steps) instead of 22.
// 64 thr/matrix, 8x8 split register tiles, FFMA2 inner product (R4 engine).
// smem: Ah, T2, Y, B (4 x 16 KB, dynamic) -> 3 blocks/SM.

#define NN 64
#define KTERM 8              // Clenshaw terms in y (i = 0..7), degree = 3*8-1 = 23
typedef unsigned long long ull;

__device__ __forceinline__ ull ffma2(ull a, ull b, ull c) {
    ull d;
    asm("fma.rn.f32x2 %0, %1, %2, %3;" : "=l"(d) : "l"(a), "l"(b), "l"(c));
    return d;
}
__device__ __forceinline__ ull dup2(float a) {
    ull d;
    asm("mov.b64 %0, {%1, %1};" : "=l"(d) : "f"(a));
    return d;
}
__device__ __forceinline__ void unpack2(ull v, float& lo, float& hi) {
    asm("mov.b64 {%0, %1}, %2;" : "=f"(lo), "=f"(hi) : "l"(v));
}
__device__ __forceinline__ ull pack2(float lo, float hi) {
    ull d;
    asm("mov.b64 %0, {%1, %2};" : "=l"(d) : "f"(lo), "f"(hi));
    return d;
}

// acc += M * B over K=64, M symmetric (A-operand read via symmetry).
__device__ __forceinline__ void mm64(unsigned aA, unsigned bA, ull acc[8][4]) {
    #pragma unroll
    for (int ar = 0; ar < 8; ++ar)
        #pragma unroll
        for (int bp = 0; bp < 4; ++bp) acc[ar][bp] = 0ULL;
    #pragma unroll 4
    for (int kk = 0; kk < NN; ++kk) {
        float4 a0, a1;
        asm("ld.shared.v4.f32 {%0,%1,%2,%3}, [%4];"
            : "=f"(a0.x), "=f"(a0.y), "=f"(a0.z), "=f"(a0.w) : "r"(aA));
        asm("ld.shared.v4.f32 {%0,%1,%2,%3}, [%4+128];"
            : "=f"(a1.x), "=f"(a1.y), "=f"(a1.z), "=f"(a1.w) : "r"(aA));
        ull b0, b1v, b2v, b3v;
        asm("ld.shared.v2.u64 {%0,%1}, [%2];"     : "=l"(b0),  "=l"(b1v) : "r"(bA));
        asm("ld.shared.v2.u64 {%0,%1}, [%2+128];" : "=l"(b2v), "=l"(b3v) : "r"(bA));
        ull ad[8];
        ad[0] = dup2(a0.x); ad[1] = dup2(a0.y); ad[2] = dup2(a0.z); ad[3] = dup2(a0.w);
        ad[4] = dup2(a1.x); ad[5] = dup2(a1.y); ad[6] = dup2(a1.z); ad[7] = dup2(a1.w);
        #pragma unroll
        for (int ar = 0; ar < 8; ++ar) {
            acc[ar][0] = ffma2(ad[ar], b0,  acc[ar][0]);
            acc[ar][1] = ffma2(ad[ar], b1v, acc[ar][1]);
            acc[ar][2] = ffma2(ad[ar], b2v, acc[ar][2]);
            acc[ar][3] = ffma2(ad[ar], b3v, acc[ar][3]);
        }
        aA += NN * 4;
        bA += NN * 4;
    }
}

__global__ __launch_bounds__(64, 3)
void logm_ps_kernel(const float* __restrict__ A, float* __restrict__ Out)
{
    extern __shared__ __align__(16) float sm[];
    float* Ah  = sm;               // Ahat  (symmetric)
    float* T2s = sm + 4096;        // T2(Ahat)
    float* Ys  = sm + 8192;        // y = T3(Ahat)
    float* Bs  = sm + 12288;       // Clenshaw b (in y)
    float* us  = sm + 16384;       // 24 folded coefficients u[i][j]

    const int tid = threadIdx.x;
    const int mat = blockIdx.x;
    const int ti  = tid >> 3;
    const int tj  = tid & 7;

    const float lo  = 0.09f, hi = 5.30f;
    const float h   = 0.5f * (hi - lo);
    const float mid = 0.5f * (hi + lo);
    const float u   = mid / h;
    const float rho = u + sqrtf(u * u - 1.0f);
    const float alpha = 1.0f / h;

    // ---- Load A -> Ahat = alpha*A - u*I ----
    {
        const float4* Ag = (const float4*)(A + (size_t)mat * (NN * NN));
        #pragma unroll
        for (int r = 0; r < 16; ++r) {
            int q = tid + (r << 6);
            float4 v = Ag[q];
            int i = q >> 4;
            int j = (q & 15) << 2;
            v.x = alpha * v.x - ((j + 0 == i) ? u : 0.0f);
            v.y = alpha * v.y - ((j + 1 == i) ? u : 0.0f);
            v.z = alpha * v.z - ((j + 2 == i) ? u : 0.0f);
            v.w = alpha * v.w - ((j + 3 == i) ? u : 0.0f);
            *(float4*)(Ah + i * NN + j) = v;
        }
    }

    // ---- Thread 0: fold Chebyshev coeffs c_0..c_23 into u[i][j] ----
    // T_{3i+j} = 2 T_j(x) T_i(y) - T_{3i-j}  (descending m)
    if (tid == 0) {
        float d[3 * KTERM];
        d[0] = logf(h * rho * 0.5f);
        float rpw = 1.0f;
        const float ir = 1.0f / rho;
        #pragma unroll
        for (int m = 1; m < 3 * KTERM; ++m) {
            rpw *= ir;
            d[m] = ((m & 1) ? 2.0f : -2.0f) * rpw / (float)m;
        }
        #pragma unroll
        for (int i = KTERM - 1; i >= 1; --i) {
            us[3 * i + 2] = 2.0f * d[3 * i + 2];
            d[3 * i - 2] -= d[3 * i + 2];
            us[3 * i + 1] = 2.0f * d[3 * i + 1];
            d[3 * i - 1] -= d[3 * i + 1];
        }
        #pragma unroll
        for (int i = 1; i < KTERM; ++i) us[3 * i] = d[3 * i];
        us[0] = d[0];
        us[1] = d[1];
        us[2] = d[2];
    }
    __syncthreads();

    const unsigned sAh = (unsigned)__cvta_generic_to_shared(Ah);
    const unsigned sT2 = (unsigned)__cvta_generic_to_shared(T2s);
    const unsigned sY  = (unsigned)__cvta_generic_to_shared(Ys);
    const unsigned sB  = (unsigned)__cvta_generic_to_shared(Bs);
    const unsigned oA  = (unsigned)(ti << 4);
    const unsigned oB  = (unsigned)(tj << 4);
    const int cA = tj << 2;
    const int cB = 32 + (tj << 2);

    ull acc[8][4];

    // ---- Phase 1: T2 = 2*Ah*Ah - I ----
    mm64(sAh + oA, sAh + oB, acc);
    #pragma unroll
    for (int ar = 0; ar < 8; ++ar) {
        const int row = ((ar & 4) << 3) + (ti << 2) + (ar & 3);
        float a0, a1, a2, a3, a4, a5, a6, a7;
        unpack2(acc[ar][0], a0, a1); unpack2(acc[ar][1], a2, a3);
        unpack2(acc[ar][2], a4, a5); unpack2(acc[ar][3], a6, a7);
        float4 n0, n1;
        n0.x = 2.0f * a0 - ((row == cA + 0) ? 1.0f : 0.0f);
        n0.y = 2.0f * a1 - ((row == cA + 1) ? 1.0f : 0.0f);
        n0.z = 2.0f * a2 - ((row == cA + 2) ? 1.0f : 0.0f);
        n0.w = 2.0f * a3 - ((row == cA + 3) ? 1.0f : 0.0f);
        n1.x = 2.0f * a4 - ((row == cB + 0) ? 1.0f : 0.0f);
        n1.y = 2.0f * a5 - ((row == cB + 1) ? 1.0f : 0.0f);
        n1.z = 2.0f * a6 - ((row == cB + 2) ? 1.0f : 0.0f);
        n1.w = 2.0f * a7 - ((row == cB + 3) ? 1.0f : 0.0f);
        *(float4*)(T2s + row * NN + cA) = n0;
        *(float4*)(T2s + row * NN + cB) = n1;
    }
    __syncthreads();

    // ---- Phase 2: Y = 2*Ah*T2 - Ah ;  B = U_7 = u0 I + u1 Ah + u2 T2 ----
    mm64(sAh + oA, sT2 + oB, acc);
    {
        const float u70 = us[3 * (KTERM - 1) + 0];
        const float u71 = us[3 * (KTERM - 1) + 1];
        const float u72 = us[3 * (KTERM - 1) + 2];
        #pragma unroll
        for (int ar = 0; ar < 8; ++ar) {
            const int row = ((ar & 4) << 3) + (ti << 2) + (ar & 3);
            float4 av0 = *(const float4*)(Ah + row * NN + cA);
            float4 av1 = *(const float4*)(Ah + row * NN + cB);
            float4 t20 = *(const float4*)(T2s + row * NN + cA);
            float4 t21 = *(const float4*)(T2s + row * NN + cB);
            float a0, a1, a2, a3, a4, a5, a6, a7;
            unpack2(acc[ar][0], a0, a1); unpack2(acc[ar][1], a2, a3);
            unpack2(acc[ar][2], a4, a5); unpack2(acc[ar][3], a6, a7);
            float4 y0, y1;
            y0.x = 2.0f * a0 - av0.x;  y0.y = 2.0f * a1 - av0.y;
            y0.z = 2.0f * a2 - av0.z;  y0.w = 2.0f * a3 - av0.w;
            y1.x = 2.0f * a4 - av1.x;  y1.y = 2.0f * a5 - av1.y;
            y1.z = 2.0f * a6 - av1.z;  y1.w = 2.0f * a7 - av1.w;
            *(float4*)(Ys + row * NN + cA) = y0;
            *(float4*)(Ys + row * NN + cB) = y1;
            float4 b0, b1;
            b0.x = u71 * av0.x + u72 * t20.x + ((row == cA + 0) ? u70 : 0.0f);
            b0.y = u71 * av0.y + u72 * t20.y + ((row == cA + 1) ? u70 : 0.0f);
            b0.z = u71 * av0.z + u72 * t20.z + ((row == cA + 2) ? u70 : 0.0f);
            b0.w = u71 * av0.w + u72 * t20.w + ((row == cA + 3) ? u70 : 0.0f);
            b1.x = u71 * av1.x + u72 * t21.x + ((row == cB + 0) ? u70 : 0.0f);
            b1.y = u71 * av1.y + u72 * t21.y + ((row == cB + 1) ? u70 : 0.0f);
            b1.z = u71 * av1.z + u72 * t21.z + ((row == cB + 2) ? u70 : 0.0f);
            b1.w = u71 * av1.w + u72 * t21.w + ((row == cB + 3) ? u70 : 0.0f);
            *(float4*)(Bs + row * NN + cA) = b0;
            *(float4*)(Bs + row * NN + cB) = b1;
        }
    }
    // b2 (= b_{i+2} tile) starts as 0
    ull b2t[8][4];
    #pragma unroll
    for (int ar = 0; ar < 8; ++ar)
        #pragma unroll
        for (int bp = 0; bp < 4; ++bp) b2t[ar][bp] = 0ULL;
    __syncthreads();

    // ---- Clenshaw in y: i = 6..1 ----
    for (int i = KTERM - 2; i >= 1; --i) {
        const float u0 = us[3 * i + 0];
        const float u1 = us[3 * i + 1];
        const float u2 = us[3 * i + 2];
        mm64(sY + oA, sB + oB, acc);
        __syncthreads();
        #pragma unroll
        for (int ar = 0; ar < 8; ++ar) {
            const int row = ((ar & 4) << 3) + (ti << 2) + (ar & 3);
            float* Bp = Bs + row * NN;
            float4 t0 = *(const float4*)(Bp + cA);     // old b1 -> next b2
            float4 t1 = *(const float4*)(Bp + cB);
            float4 av0 = *(const float4*)(Ah + row * NN + cA);
            float4 av1 = *(const float4*)(Ah + row * NN + cB);
            float4 t20 = *(const float4*)(T2s + row * NN + cA);
            float4 t21 = *(const float4*)(T2s + row * NN + cB);
            float a0, a1, a2, a3, a4, a5, a6, a7;
            unpack2(acc[ar][0], a0, a1); unpack2(acc[ar][1], a2, a3);
            unpack2(acc[ar][2], a4, a5); unpack2(acc[ar][3], a6, a7);
            float o0, o1, o2, o3, o4, o5, o6, o7;
            unpack2(b2t[ar][0], o0, o1); unpack2(b2t[ar][1], o2, o3);
            unpack2(b2t[ar][2], o4, o5); unpack2(b2t[ar][3], o6, o7);
            float4 n0, n1;
            n0.x = 2.0f * a0 - o0 + u1 * av0.x + u2 * t20.x + ((row == cA + 0) ? u0 : 0.0f);
            n0.y = 2.0f * a1 - o1 + u1 * av0.y + u2 * t20.y + ((row == cA + 1) ? u0 : 0.0f);
            n0.z = 2.0f * a2 - o2 + u1 * av0.z + u2 * t20.z + ((row == cA + 2) ? u0 : 0.0f);
            n0.w = 2.0f * a3 - o3 + u1 * av0.w + u2 * t20.w + ((row == cA + 3) ? u0 : 0.0f);
            n1.x = 2.0f * a4 - o4 + u1 * av1.x + u2 * t21.x + ((row == cB + 0) ? u0 : 0.0f);
            n1.y = 2.0f * a5 - o5 + u1 * av1.y + u2 * t21.y + ((row == cB + 1) ? u0 : 0.0f);
            n1.z = 2.0f * a6 - o6 + u1 * av1.z + u2 * t21.z + ((row == cB + 2) ? u0 : 0.0f);
            n1.w = 2.0f * a7 - o7 + u1 * av1.w + u2 * t21.w + ((row == cB + 3) ? u0 : 0.0f);
            *(float4*)(Bp + cA) = n0;
            *(float4*)(Bp + cB) = n1;
            b2t[ar][0] = pack2(t0.x, t0.y);
            b2t[ar][1] = pack2(t0.z, t0.w);
            b2t[ar][2] = pack2(t1.x, t1.y);
            b2t[ar][3] = pack2(t1.z, t1.w);
        }
        __syncthreads();
    }

    // ---- Final: out = U_0 + y*b1 - b2 ----
    {
        const float u0 = us[0];
        const float u1 = us[1];
        const float u2 = us[2];
        mm64(sY + oA, sB + oB, acc);
        float* Og = Out + (size_t)mat * (NN * NN);
        #pragma unroll
        for (int ar = 0; ar < 8; ++ar) {
            const int row = ((ar & 4) << 3) + (ti << 2) + (ar & 3);
            float4 av0 = *(const float4*)(Ah + row * NN + cA);
            float4 av1 = *(const float4*)(Ah + row * NN + cB);
            float4 t20 = *(const float4*)(T2s + row * NN + cA);
            float4 t21 = *(const float4*)(T2s + row * NN + cB);
            float a0, a1, a2, a3, a4, a5, a6, a7;
            unpack2(acc[ar][0], a0, a1); unpack2(acc[ar][1], a2, a3);
            unpack2(acc[ar][2], a4, a5); unpack2(acc[ar][3], a6, a7);
            float o0, o1, o2, o3, o4, o5, o6, o7;
            unpack2(b2t[ar][0], o0, o1); unpack2(b2t[ar][1], o2, o3);
            unpack2(b2t[ar][2], o4, o5); unpack2(b2t[ar][3], o6, o7);
            float4 n0, n1;
            n0.x = a0 - o0 + u1 * av0.x + u2 * t20.x + ((row == cA + 0) ? u0 : 0.0f);
            n0.y = a1 - o1 + u1 * av0.y + u2 * t20.y + ((row == cA + 1) ? u0 : 0.0f);
            n0.z = a2 - o2 + u1 * av0.z + u2 * t20.z + ((row == cA + 2) ? u0 : 0.0f);
            n0.w = a3 - o3 + u1 * av0.w + u2 * t20.w + ((row == cA + 3) ? u0 : 0.0f);
            n1.x = a4 - o4 + u1 * av1.x + u2 * t21.x + ((row == cB + 0) ? u0 : 0.0f);
            n1.y = a5 - o5 + u1 * av1.y + u2 * t21.y + ((row == cB + 1) ? u0 : 0.0f);
            n1.z = a6 - o6 + u1 * av1.z + u2 * t21.z + ((row == cB + 2) ? u0 : 0.0f);
            n1.w = a7 - o7 + u1 * av1.w + u2 * t21.w + ((row == cB + 3) ? u0 : 0.0f);
            *(float4*)(Og + row * NN + cA) = n0;
            *(float4*)(Og + row * NN + cB) = n1;
        }
    }
}

#define SMEM_BYTES ((16384 + 32) * 4)

extern "C" void kernel_launch(void* const* d_in, const int* in_sizes, int n_in,
                              void* d_out, int out_size) {
    const float* x = (const float*)d_in[0];
    float* out = (float*)d_out;
    int nmat = in_sizes[0] / (NN * NN);
    cudaFuncSetAttribute(logm_ps_kernel,
                         cudaFuncAttributeMaxDynamicSharedMemorySize, SMEM_BYTES);
    logm_ps_kernel<<<nmat, 64, SMEM_BYTES>>>(x, out);
}

// round 10
// speedup vs baseline: 6.8494x; 1.0955x over previous
#include <cuda_runtime.h>
#include <math.h>

// Batched log(A) for SPD 64x64, degree-23 Chebyshev via Paterson-Stockmeyer
// in the Chebyshev basis (s=3, k=8): 9 matmuls. R6: 3 smem arrays only
// (Y overwrites Ah in place; per-thread Ah tile kept in registers) ->
// 48KB/block -> 4 blocks/SM (8 warps).

#define NN 64
#define KTERM 8
typedef unsigned long long ull;

__device__ __forceinline__ ull ffma2(ull a, ull b, ull c) {
    ull d;
    asm("fma.rn.f32x2 %0, %1, %2, %3;" : "=l"(d) : "l"(a), "l"(b), "l"(c));
    return d;
}
__device__ __forceinline__ ull dup2(float a) {
    ull d;
    asm("mov.b64 %0, {%1, %1};" : "=l"(d) : "f"(a));
    return d;
}
__device__ __forceinline__ void unpack2(ull v, float& lo, float& hi) {
    asm("mov.b64 {%0, %1}, %2;" : "=f"(lo), "=f"(hi) : "l"(v));
}
__device__ __forceinline__ ull pack2(float lo, float hi) {
    ull d;
    asm("mov.b64 %0, {%1, %2};" : "=l"(d) : "f"(lo), "f"(hi));
    return d;
}

// acc = M * B over K=64, M symmetric (A-operand read via symmetry).
__device__ __forceinline__ void mm64(unsigned aA, unsigned bA, ull acc[8][4]) {
    #pragma unroll
    for (int ar = 0; ar < 8; ++ar)
        #pragma unroll
        for (int bp = 0; bp < 4; ++bp) acc[ar][bp] = 0ULL;
    #pragma unroll 4
    for (int kk = 0; kk < NN; ++kk) {
        float4 a0, a1;
        asm("ld.shared.v4.f32 {%0,%1,%2,%3}, [%4];"
            : "=f"(a0.x), "=f"(a0.y), "=f"(a0.z), "=f"(a0.w) : "r"(aA));
        asm("ld.shared.v4.f32 {%0,%1,%2,%3}, [%4+128];"
            : "=f"(a1.x), "=f"(a1.y), "=f"(a1.z), "=f"(a1.w) : "r"(aA));
        ull b0, b1v, b2v, b3v;
        asm("ld.shared.v2.u64 {%0,%1}, [%2];"     : "=l"(b0),  "=l"(b1v) : "r"(bA));
        asm("ld.shared.v2.u64 {%0,%1}, [%2+128];" : "=l"(b2v), "=l"(b3v) : "r"(bA));
        ull ad[8];
        ad[0] = dup2(a0.x); ad[1] = dup2(a0.y); ad[2] = dup2(a0.z); ad[3] = dup2(a0.w);
        ad[4] = dup2(a1.x); ad[5] = dup2(a1.y); ad[6] = dup2(a1.z); ad[7] = dup2(a1.w);
        #pragma unroll
        for (int ar = 0; ar < 8; ++ar) {
            acc[ar][0] = ffma2(ad[ar], b0,  acc[ar][0]);
            acc[ar][1] = ffma2(ad[ar], b1v, acc[ar][1]);
            acc[ar][2] = ffma2(ad[ar], b2v, acc[ar][2]);
            acc[ar][3] = ffma2(ad[ar], b3v, acc[ar][3]);
        }
        aA += NN * 4;
        bA += NN * 4;
    }
}

__global__ __launch_bounds__(64, 4)
void logm_ps_kernel(const float* __restrict__ A, float* __restrict__ Out)
{
    extern __shared__ __align__(16) float sm[];
    float* M0 = sm;               // Ahat, later overwritten by Y = T3
    float* T2s = sm + 4096;       // T2(Ahat)
    float* Bs  = sm + 8192;       // Clenshaw b (in y)
    float* us  = sm + 12288;      // 24 folded coefficients

    const int tid = threadIdx.x;
    const int mat = blockIdx.x;
    const int ti  = tid >> 3;
    const int tj  = tid & 7;

    const float lo  = 0.09f, hi = 5.30f;
    const float h   = 0.5f * (hi - lo);
    const float mid = 0.5f * (hi + lo);
    const float u   = mid / h;
    const float rho = u + sqrtf(u * u - 1.0f);
    const float alpha = 1.0f / h;

    // ---- Load A -> Ahat = alpha*A - u*I ----
    {
        const float4* Ag = (const float4*)(A + (size_t)mat * (NN * NN));
        #pragma unroll
        for (int r = 0; r < 16; ++r) {
            int q = tid + (r << 6);
            float4 v = Ag[q];
            int i = q >> 4;
            int j = (q & 15) << 2;
            v.x = alpha * v.x - ((j + 0 == i) ? u : 0.0f);
            v.y = alpha * v.y - ((j + 1 == i) ? u : 0.0f);
            v.z = alpha * v.z - ((j + 2 == i) ? u : 0.0f);
            v.w = alpha * v.w - ((j + 3 == i) ? u : 0.0f);
            *(float4*)(M0 + i * NN + j) = v;
        }
    }

    // ---- Thread 0: fold Chebyshev coeffs c_0..c_23 into u[i][j] ----
    if (tid == 0) {
        float d[3 * KTERM];
        d[0] = logf(h * rho * 0.5f);
        float rpw = 1.0f;
        const float ir = 1.0f / rho;
        #pragma unroll
        for (int m = 1; m < 3 * KTERM; ++m) {
            rpw *= ir;
            d[m] = ((m & 1) ? 2.0f : -2.0f) * rpw / (float)m;
        }
        #pragma unroll
        for (int i = KTERM - 1; i >= 1; --i) {
            us[3 * i + 2] = 2.0f * d[3 * i + 2];
            d[3 * i - 2] -= d[3 * i + 2];
            us[3 * i + 1] = 2.0f * d[3 * i + 1];
            d[3 * i - 1] -= d[3 * i + 1];
        }
        #pragma unroll
        for (int i = 1; i < KTERM; ++i) us[3 * i] = d[3 * i];
        us[0] = d[0];
        us[1] = d[1];
        us[2] = d[2];
    }
    __syncthreads();

    const unsigned sM0 = (unsigned)__cvta_generic_to_shared(M0);
    const unsigned sT2 = (unsigned)__cvta_generic_to_shared(T2s);
    const unsigned sB  = (unsigned)__cvta_generic_to_shared(Bs);
    const unsigned oA  = (unsigned)(ti << 4);
    const unsigned oB  = (unsigned)(tj << 4);
    const int cA = tj << 2;
    const int cB = 32 + (tj << 2);

    // ---- Stash this thread's Ahat tile in registers (epilogue operand) ----
    float4 ahr[8][2];
    #pragma unroll
    for (int ar = 0; ar < 8; ++ar) {
        const int row = ((ar & 4) << 3) + (ti << 2) + (ar & 3);
        ahr[ar][0] = *(const float4*)(M0 + row * NN + cA);
        ahr[ar][1] = *(const float4*)(M0 + row * NN + cB);
    }

    ull acc[8][4];

    // ---- Phase 1: T2 = 2*Ah*Ah - I ----
    mm64(sM0 + oA, sM0 + oB, acc);
    #pragma unroll
    for (int ar = 0; ar < 8; ++ar) {
        const int row = ((ar & 4) << 3) + (ti << 2) + (ar & 3);
        float a0, a1, a2, a3, a4, a5, a6, a7;
        unpack2(acc[ar][0], a0, a1); unpack2(acc[ar][1], a2, a3);
        unpack2(acc[ar][2], a4, a5); unpack2(acc[ar][3], a6, a7);
        float4 n0, n1;
        n0.x = 2.0f * a0 - ((row == cA + 0) ? 1.0f : 0.0f);
        n0.y = 2.0f * a1 - ((row == cA + 1) ? 1.0f : 0.0f);
        n0.z = 2.0f * a2 - ((row == cA + 2) ? 1.0f : 0.0f);
        n0.w = 2.0f * a3 - ((row == cA + 3) ? 1.0f : 0.0f);
        n1.x = 2.0f * a4 - ((row == cB + 0) ? 1.0f : 0.0f);
        n1.y = 2.0f * a5 - ((row == cB + 1) ? 1.0f : 0.0f);
        n1.z = 2.0f * a6 - ((row == cB + 2) ? 1.0f : 0.0f);
        n1.w = 2.0f * a7 - ((row == cB + 3) ? 1.0f : 0.0f);
        *(float4*)(T2s + row * NN + cA) = n0;
        *(float4*)(T2s + row * NN + cB) = n1;
    }
    __syncthreads();

    // ---- Phase 2: acc = Ah*T2; then Y = 2*acc - Ah overwrites M0;
    //      B = U_7 = u0 I + u1 Ah + u2 T2 ----
    mm64(sM0 + oA, sT2 + oB, acc);
    __syncthreads();               // all reads of M0 (Ah) complete before overwrite
    {
        const float u70 = us[3 * (KTERM - 1) + 0];
        const float u71 = us[3 * (KTERM - 1) + 1];
        const float u72 = us[3 * (KTERM - 1) + 2];
        #pragma unroll
        for (int ar = 0; ar < 8; ++ar) {
            const int row = ((ar & 4) << 3) + (ti << 2) + (ar & 3);
            float4 av0 = ahr[ar][0];
            float4 av1 = ahr[ar][1];
            float4 t20 = *(const float4*)(T2s + row * NN + cA);
            float4 t21 = *(const float4*)(T2s + row * NN + cB);
            float a0, a1, a2, a3, a4, a5, a6, a7;
            unpack2(acc[ar][0], a0, a1); unpack2(acc[ar][1], a2, a3);
            unpack2(acc[ar][2], a4, a5); unpack2(acc[ar][3], a6, a7);
            float4 y0, y1;
            y0.x = 2.0f * a0 - av0.x;  y0.y = 2.0f * a1 - av0.y;
            y0.z = 2.0f * a2 - av0.z;  y0.w = 2.0f * a3 - av0.w;
            y1.x = 2.0f * a4 - av1.x;  y1.y = 2.0f * a5 - av1.y;
            y1.z = 2.0f * a6 - av1.z;  y1.w = 2.0f * a7 - av1.w;
            *(float4*)(M0 + row * NN + cA) = y0;
            *(float4*)(M0 + row * NN + cB) = y1;
            float4 b0, b1;
            b0.x = u71 * av0.x + u72 * t20.x + ((row == cA + 0) ? u70 : 0.0f);
            b0.y = u71 * av0.y + u72 * t20.y + ((row == cA + 1) ? u70 : 0.0f);
            b0.z = u71 * av0.z + u72 * t20.z + ((row == cA + 2) ? u70 : 0.0f);
            b0.w = u71 * av0.w + u72 * t20.w + ((row == cA + 3) ? u70 : 0.0f);
            b1.x = u71 * av1.x + u72 * t21.x + ((row == cB + 0) ? u70 : 0.0f);
            b1.y = u71 * av1.y + u72 * t21.y + ((row == cB + 1) ? u70 : 0.0f);
            b1.z = u71 * av1.z + u72 * t21.z + ((row == cB + 2) ? u70 : 0.0f);
            b1.w = u71 * av1.w + u72 * t21.w + ((row == cB + 3) ? u70 : 0.0f);
            *(float4*)(Bs + row * NN + cA) = b0;
            *(float4*)(Bs + row * NN + cB) = b1;
        }
    }
    ull b2t[8][4];
    #pragma unroll
    for (int ar = 0; ar < 8; ++ar)
        #pragma unroll
        for (int bp = 0; bp < 4; ++bp) b2t[ar][bp] = 0ULL;
    __syncthreads();

    // ---- Clenshaw in y: i = 6..1  (M0 now holds Y) ----
    for (int i = KTERM - 2; i >= 1; --i) {
        const float u0 = us[3 * i + 0];
        const float u1 = us[3 * i + 1];
        const float u2 = us[3 * i + 2];
        mm64(sM0 + oA, sB + oB, acc);
        __syncthreads();
        #pragma unroll
        for (int ar = 0; ar < 8; ++ar) {
            const int row = ((ar & 4) << 3) + (ti << 2) + (ar & 3);
            float* Bp = Bs + row * NN;
            float4 t0 = *(const float4*)(Bp + cA);     // old b1 -> next b2
            float4 t1 = *(const float4*)(Bp + cB);
            float4 av0 = ahr[ar][0];
            float4 av1 = ahr[ar][1];
            float4 t20 = *(const float4*)(T2s + row * NN + cA);
            float4 t21 = *(const float4*)(T2s + row * NN + cB);
            float a0, a1, a2, a3, a4, a5, a6, a7;
            unpack2(acc[ar][0], a0, a1); unpack2(acc[ar][1], a2, a3);
            unpack2(acc[ar][2], a4, a5); unpack2(acc[ar][3], a6, a7);
            float o0, o1, o2, o3, o4, o5, o6, o7;
            unpack2(b2t[ar][0], o0, o1); unpack2(b2t[ar][1], o2, o3);
            unpack2(b2t[ar][2], o4, o5); unpack2(b2t[ar][3], o6, o7);
            float4 n0, n1;
            n0.x = 2.0f * a0 - o0 + u1 * av0.x + u2 * t20.x + ((row == cA + 0) ? u0 : 0.0f);
            n0.y = 2.0f * a1 - o1 + u1 * av0.y + u2 * t20.y + ((row == cA + 1) ? u0 : 0.0f);
            n0.z = 2.0f * a2 - o2 + u1 * av0.z + u2 * t20.z + ((row == cA + 2) ? u0 : 0.0f);
            n0.w = 2.0f * a3 - o3 + u1 * av0.w + u2 * t20.w + ((row == cA + 3) ? u0 : 0.0f);
            n1.x = 2.0f * a4 - o4 + u1 * av1.x + u2 * t21.x + ((row == cB + 0) ? u0 : 0.0f);
            n1.y = 2.0f * a5 - o5 + u1 * av1.y + u2 * t21.y + ((row == cB + 1) ? u0 : 0.0f);
            n1.z = 2.0f * a6 - o6 + u1 * av1.z + u2 * t21.z + ((row == cB + 2) ? u0 : 0.0f);
            n1.w = 2.0f * a7 - o7 + u1 * av1.w + u2 * t21.w + ((row == cB + 3) ? u0 : 0.0f);
            *(float4*)(Bp + cA) = n0;
            *(float4*)(Bp + cB) = n1;
            b2t[ar][0] = pack2(t0.x, t0.y);
            b2t[ar][1] = pack2(t0.z, t0.w);
            b2t[ar][2] = pack2(t1.x, t1.y);
            b2t[ar][3] = pack2(t1.z, t1.w);
        }
        __syncthreads();
    }

    // ---- Final: out = U_0 + y*b1 - b2 ----
    {
        const float u0 = us[0];
        const float u1 = us[1];
        const float u2 = us[2];
        mm64(sM0 + oA, sB + oB, acc);
        float* Og = Out + (size_t)mat * (NN * NN);
        #pragma unroll
        for (int ar = 0; ar < 8; ++ar) {
            const int row = ((ar & 4) << 3) + (ti << 2) + (ar & 3);
            float4 av0 = ahr[ar][0];
            float4 av1 = ahr[ar][1];
            float4 t20 = *(const float4*)(T2s + row * NN + cA);
            float4 t21 = *(const float4*)(T2s + row * NN + cB);
            float a0, a1, a2, a3, a4, a5, a6, a7;
            unpack2(acc[ar][0], a0, a1); unpack2(acc[ar][1], a2, a3);
            unpack2(acc[ar][2], a4, a5); unpack2(acc[ar][3], a6, a7);
            float o0, o1, o2, o3, o4, o5, o6, o7;
            unpack2(b2t[ar][0], o0, o1); unpack2(b2t[ar][1], o2, o3);
            unpack2(b2t[ar][2], o4, o5); unpack2(b2t[ar][3], o6, o7);
            float4 n0, n1;
            n0.x = a0 - o0 + u1 * av0.x + u2 * t20.x + ((row == cA + 0) ? u0 : 0.0f);
            n0.y = a1 - o1 + u1 * av0.y + u2 * t20.y + ((row == cA + 1) ? u0 : 0.0f);
            n0.z = a2 - o2 + u1 * av0.z + u2 * t20.z + ((row == cA + 2) ? u0 : 0.0f);
            n0.w = a3 - o3 + u1 * av0.w + u2 * t20.w + ((row == cA + 3) ? u0 : 0.0f);
            n1.x = a4 - o4 + u1 * av1.x + u2 * t21.x + ((row == cB + 0) ? u0 : 0.0f);
            n1.y = a5 - o5 + u1 * av1.y + u2 * t21.y + ((row == cB + 1) ? u0 : 0.0f);
            n1.z = a6 - o6 + u1 * av1.z + u2 * t21.z + ((row == cB + 2) ? u0 : 0.0f);
            n1.w = a7 - o7 + u1 * av1.w + u2 * t21.w + ((row == cB + 3) ? u0 : 0.0f);
            *(float4*)(Og + row * NN + cA) = n0;
            *(float4*)(Og + row * NN + cB) = n1;
        }
    }
}

#define SMEM_BYTES ((12288 + 32) * 4)

extern "C" void kernel_launch(void* const* d_in, const int* in_sizes, int n_in,
                              void* d_out, int out_size) {
    const float* x = (const float*)d_in[0];
    float* out = (float*)d_out;
    int nmat = in_sizes[0] / (NN * NN);
    cudaFuncSetAttribute(logm_ps_kernel,
                         cudaFuncAttributeMaxDynamicSharedMemorySize, SMEM_BYTES);
    logm_ps_kernel<<<nmat, 64, SMEM_BYTES>>>(x, out);
}